// round 2
// baseline (speedup 1.0000x reference)
#include <cuda_runtime.h>
#include <math.h>

#define HH   64
#define WW   64
#define DIMC 512     // per-axis sinusoid width
#define ODIM 256     // output dim
#define BATCH 8

// E[h][k]: embed of arange(64) (identical for x and y axes)
__device__ float g_E[HH][DIMC];
// C[r][o]: r<64 -> A[h][o] (W cols 0:512), r>=64 -> B[w][o] (W cols 512:1024)
__device__ float g_C[2 * HH][ODIM];

// ---------------------------------------------------------------------------
// k0: compute embeddings E and zero C.  32768 threads, one elem each.
// embed col k<256: sin(z / 1000^((2k+1)/512)); col 256+k: cos(z / 1000^((2k)/512))
// ---------------------------------------------------------------------------
__global__ __launch_bounds__(256) void k0_embed_zero() {
    int idx = blockIdx.x * blockDim.x + threadIdx.x;   // 0 .. 32767
    if (idx < HH * DIMC) {
        int h = idx >> 9;          // /512
        int k = idx & 511;
        float expo, val;
        float z = (float)h;
        if (k < 256) {
            expo = (float)(2 * k + 1) * (1.0f / 512.0f);
            float freq = expf(-expo * 6.907755278982137f);   // 1000^(-expo)
            val = sinf(z * freq);
        } else {
            expo = (float)(2 * (k - 256)) * (1.0f / 512.0f);
            float freq = expf(-expo * 6.907755278982137f);
            val = cosf(z * freq);
        }
        g_E[h][k] = val;
        // zero the accumulator (same element count: 128*256 = 32768)
        ((float*)g_C)[idx] = 0.0f;
    }
}

// ---------------------------------------------------------------------------
// k1: split-K GEMM  C[half*64+m][o] += sum_k E[m][k] * W[o][half*512 + k]
// grid: (16 K-tiles of 32, 4 N-tiles of 64, 2 halves) = 128 blocks, 256 thr.
// Each block: M=64 (full), N=64, K=32; thread = 4x4 micro-tile.
// W is read exactly once chip-wide (K,N tiles partition it).
// ---------------------------------------------------------------------------
__global__ __launch_bounds__(256) void k1_gemm(const float* __restrict__ W) {
    const int k0   = blockIdx.x * 32;
    const int n0   = blockIdx.y * 64;
    const int half = blockIdx.z;
    const int off  = half * DIMC;          // column offset into W rows (len 1024)

    __shared__ float Es[64][36];           // [m][k]  (pad 36 vs bank conflicts)
    __shared__ float Ws[32][68];           // [k][n]  (pad 68: float4-aligned rows)

    const int t = threadIdx.x;

    // stage E tile: 64 rows x 32 k, coalesced over k
    #pragma unroll
    for (int e = t; e < 64 * 32; e += 256) {
        int k = e & 31, m = e >> 5;
        Es[m][k] = g_E[m][k0 + k];
    }
    // stage W tile (transposed): rows o0..o0+63, cols k0..k0+31, coalesced over k
    #pragma unroll
    for (int e = t; e < 64 * 32; e += 256) {
        int k = e & 31, i = e >> 5;
        Ws[k][i] = W[(size_t)(n0 + i) * (2 * DIMC) + off + k0 + k];
    }
    __syncthreads();

    const int tx = t & 15, ty = t >> 4;    // 16 x 16 threads
    const int mb = ty * 4, nb = tx * 4;    // 4x4 micro-tile

    float acc[4][4] = {};
    #pragma unroll 8
    for (int k = 0; k < 32; k++) {
        float4 b = *(const float4*)&Ws[k][nb];
        float a0 = Es[mb + 0][k];
        float a1 = Es[mb + 1][k];
        float a2 = Es[mb + 2][k];
        float a3 = Es[mb + 3][k];
        acc[0][0] += a0 * b.x; acc[0][1] += a0 * b.y; acc[0][2] += a0 * b.z; acc[0][3] += a0 * b.w;
        acc[1][0] += a1 * b.x; acc[1][1] += a1 * b.y; acc[1][2] += a1 * b.z; acc[1][3] += a1 * b.w;
        acc[2][0] += a2 * b.x; acc[2][1] += a2 * b.y; acc[2][2] += a2 * b.z; acc[2][3] += a2 * b.w;
        acc[3][0] += a3 * b.x; acc[3][1] += a3 * b.y; acc[3][2] += a3 * b.z; acc[3][3] += a3 * b.w;
    }

    const int rbase = half * 64 + mb;
    #pragma unroll
    for (int i = 0; i < 4; i++)
        #pragma unroll
        for (int j = 0; j < 4; j++)
            atomicAdd(&g_C[rbase + i][n0 + nb + j], acc[i][j]);
}

// ---------------------------------------------------------------------------
// k2: out[b][h][w][o] = C[h][o] + C[64+w][o], broadcast over b (8x).
// 1024 blocks x 256 threads; each block handles 4 (h,w) pairs; each thread
// one float4 of the 256-wide row, stored 8 times. Fully coalesced 512B/warp.
// ---------------------------------------------------------------------------
__global__ __launch_bounds__(256) void k2_write(float* __restrict__ out) {
    const int t  = threadIdx.x;
    const int pg = blockIdx.x * 4 + (t >> 6);   // 0..4095 pair index
    const int q  = t & 63;                      // float4 index within row
    const int h  = pg >> 6;
    const int w  = pg & 63;

    float4 a = *(const float4*)&g_C[h][q * 4];
    float4 b = *(const float4*)&g_C[64 + w][q * 4];
    float4 v;
    v.x = a.x + b.x; v.y = a.y + b.y; v.z = a.z + b.z; v.w = a.w + b.w;

    size_t base = (((size_t)h * 64 + w) * 256) + (size_t)q * 4;
    const size_t bstride = (size_t)64 * 64 * 256;   // per-batch stride
    #pragma unroll
    for (int bt = 0; bt < BATCH; bt++) {
        *(float4*)&out[base + (size_t)bt * bstride] = v;
    }
}

// ---------------------------------------------------------------------------
extern "C" void kernel_launch(void* const* d_in, const int* in_sizes, int n_in,
                              void* d_out, int out_size) {
    const float* W = (const float*)d_in[0];   // W_im: (256, 1024) fp32
    float* out = (float*)d_out;               // (8, 64, 64, 256, 1) fp32

    k0_embed_zero<<<128, 256>>>();
    dim3 g1(16, 4, 2);
    k1_gemm<<<g1, 256>>>(W);
    k2_write<<<1024, 256>>>(out);
}